// round 4
// baseline (speedup 1.0000x reference)
#include <cuda_runtime.h>
#include <cuda_bf16.h>
#include <math.h>

// Problem constants
#define BB 8
#define MM 4096
#define WW 128
#define CC 32
#define NNB 16
#define BM (BB*MM)            // 32768
#define MC (MM*CC)            // 131072
#define EPS 1e-5f

// -------------------- scratch (device globals; no allocs) --------------------
__device__ float g_attn0[MM*NNB];
__device__ float g_attn1[MM*NNB];
__device__ int   g_nbr  [MM*NNB];
__device__ float g_y [BM*64];        // layer0 GEMM out: [b][m][0..31]=x@w1^T, [32..63]=x@w2^T
__device__ float g_z [BM*64];        // layer1 GEMM out
__device__ float g_h0[BM*CC];        // pre-BN layer0
__device__ float g_h1[BM*CC];        // pre-BN layer1
__device__ float g_sp[64*512];       // per-block BN partials (sum rows 0..31, sq rows 32..63)
__device__ float g_bnsc[64];         // BN scale: [0..31] layer0, [32..63] layer1
__device__ float g_bnsh[64];         // BN shift
__device__ float g_fc1p[32*2048];    // split-K partials for FC1: [kc][b*256+o]
__device__ unsigned g_cnt[4];        // zero-init; self-resetting last-block counters

// packed fp32x2 FMA (Blackwell): d = a*b + d on both 32-bit lanes
__device__ __forceinline__ void ffma2(unsigned long long& d, unsigned long long a, unsigned long long b) {
    asm("fma.rn.f32x2 %0, %1, %2, %0;" : "+l"(d) : "l"(a), "l"(b));
}
__device__ __forceinline__ float f32x2_hsum(unsigned long long v) {
    float lo = __uint_as_float((unsigned)(v & 0xffffffffull));
    float hi = __uint_as_float((unsigned)(v >> 32));
    return lo + hi;
}

// -------------------- K1: fused gemm0 (blocks 0..255) + edge attention (256..511) ----
__global__ void __launch_bounds__(256) k_pre(const float* __restrict__ x,
                       const float* __restrict__ w1, const float* __restrict__ w2,
                       const float* __restrict__ pseudo, const int* __restrict__ L_idx,
                       const float* __restrict__ edge_w, const float* __restrict__ edge_b,
                       const float* __restrict__ mu0, const float* __restrict__ sg0,
                       const float* __restrict__ mu1, const float* __restrict__ sg1) {
    __shared__ float2 xs2[16][129];
    __shared__ float2 ws2[16][65];
    if (blockIdx.x >= 256) {
        // ---------------- attention part: thread-per-edge ----------------
        int e = (blockIdx.x - 256) * blockDim.x + threadIdx.x;  // 0..65535
        int r = e >> 4;
        int lane = threadIdx.x & 31;
        int nb = L_idx[e] - r * MM;
        float2 p = *(const float2*)(pseudo + e * 2);
        float emb[5];
        #pragma unroll
        for (int d = 0; d < 5; d++)
            emb[d] = fmaf(p.x, edge_w[d*2], fmaf(p.y, edge_w[d*2+1], edge_b[d]));
        float w0 = 0.f, w1v = 0.f;
        #pragma unroll
        for (int j = 0; j < 4; j++) {
            float q0 = 0.f, q1 = 0.f;
            #pragma unroll
            for (int d = 0; d < 5; d++) {
                float u0 = emb[d] - mu0[j*5+d]; q0 = fmaf(u0*u0, sg0[j*5+d], q0);
                float u1 = emb[d] - mu1[j*5+d]; q1 = fmaf(u1*u1, sg1[j*5+d], q1);
            }
            w0  += __expf(-0.5f * q0);
            w1v += __expf(-0.5f * q1);
        }
        float mx0 = w0, mx1 = w1v;
        #pragma unroll
        for (int off = 8; off; off >>= 1) {
            mx0 = fmaxf(mx0, __shfl_xor_sync(0xffffffffu, mx0, off));
            mx1 = fmaxf(mx1, __shfl_xor_sync(0xffffffffu, mx1, off));
        }
        float e0 = __expf(w0 - mx0), e1 = __expf(w1v - mx1);
        float s0 = e0, s1 = e1;
        #pragma unroll
        for (int off = 8; off; off >>= 1) {
            s0 += __shfl_xor_sync(0xffffffffu, s0, off);
            s1 += __shfl_xor_sync(0xffffffffu, s1, off);
        }
        // dedup: `.at[].set` keeps the LAST duplicate -> only highest lane survives
        unsigned segmask = (lane < 16) ? 0x0000FFFFu : 0xFFFF0000u;
        unsigned m = __match_any_sync(0xffffffffu, nb) & segmask;
        bool keep = (lane == (31 - __clz(m)));
        g_attn0[e] = keep ? e0 / s0 : 0.f;
        g_attn1[e] = keep ? e1 / s1 : 0.f;
        g_nbr[e]   = nb;
        return;
    }
    // ---------------- gemm0: y = x @ [w1;w2]^T, tile 128x64, FFMA2 ----------------
    int m0 = (blockIdx.x & 31) * 128;
    int b  = blockIdx.x >> 5;
    const float* xp = x + ((size_t)b * MM + m0) * WW;
    int tc = threadIdx.x & 15, tr = threadIdx.x >> 4;
    unsigned long long acc[8][4];
    #pragma unroll
    for (int i = 0; i < 8; i++)
        #pragma unroll
        for (int j = 0; j < 4; j++) acc[i][j] = 0ull;

    #pragma unroll 1
    for (int kc = 0; kc < 4; kc++) {
        for (int i = threadIdx.x; i < 1024; i += 256) {
            int r = i >> 3, q = i & 7;
            float4 v = *(const float4*)(xp + r * WW + kc * 32 + q * 4);
            xs2[2*q  ][r] = make_float2(v.x, v.y);
            xs2[2*q+1][r] = make_float2(v.z, v.w);
        }
        for (int i = threadIdx.x; i < 512; i += 256) {
            int r = i >> 3, q = i & 7;
            const float* wp = (r < 32) ? (w1 + r * WW) : (w2 + (r - 32) * WW);
            float4 v = *(const float4*)(wp + kc * 32 + q * 4);
            ws2[2*q  ][r] = make_float2(v.x, v.y);
            ws2[2*q+1][r] = make_float2(v.z, v.w);
        }
        __syncthreads();
        #pragma unroll 4
        for (int kp = 0; kp < 16; kp++) {
            unsigned long long av[8], bv[4];
            #pragma unroll
            for (int i = 0; i < 8; i++) av[i] = *(const unsigned long long*)&xs2[kp][tr + 16*i];
            #pragma unroll
            for (int j = 0; j < 4; j++) bv[j] = *(const unsigned long long*)&ws2[kp][tc + 16*j];
            #pragma unroll
            for (int i = 0; i < 8; i++)
                #pragma unroll
                for (int j = 0; j < 4; j++) ffma2(acc[i][j], av[i], bv[j]);
        }
        __syncthreads();
    }
    float* yp = g_y + ((size_t)b * MM + m0) * 64;
    #pragma unroll
    for (int i = 0; i < 8; i++)
        #pragma unroll
        for (int j = 0; j < 4; j++)
            yp[(tr + 16*i) * 64 + tc + 16*j] = f32x2_hsum(acc[i][j]);
}

// -------------------- K2/K4: gather + BN partials + last-block BN finalize --------------------
// 512 blocks x 512 threads; warp handles 4 (b,m) rows; lane = channel.
__global__ void __launch_bounds__(512) k_gather(int layer,
                                                const float* __restrict__ b1,
                                                const float* __restrict__ b2,
                                                const float* __restrict__ bng,
                                                const float* __restrict__ bnb) {
    __shared__ float sarr[16][33];
    __shared__ float qarr[16][33];
    __shared__ float statf[64];
    __shared__ unsigned is_last;
    int wid = threadIdx.x >> 5, lane = threadIdx.x & 31;
    const float* ysrc = layer ? g_z : g_y;
    const float* attn = layer ? g_attn1 : g_attn0;
    float*       hout = layer ? g_h1 : g_h0;
    float bias = b1[lane] + b2[lane];
    float s = 0.f, q = 0.f;
    int base = blockIdx.x * 64 + wid * 4;
    #pragma unroll
    for (int rr = 0; rr < 4; rr++) {
        int gw = base + rr;
        int b  = gw >> 12, m = gw & (MM - 1);
        const float* yb = ysrc + (size_t)b * MM * 64;
        float acc = 0.f;
        #pragma unroll
        for (int n = 0; n < NNB; n++) {
            float a = attn[m * NNB + n];
            int nb = g_nbr[m * NNB + n];
            acc = fmaf(a, yb[(size_t)nb * 64 + lane], acc);
        }
        float h = acc + yb[(size_t)m * 64 + 32 + lane] + bias;
        hout[(size_t)gw * CC + lane] = h;
        s += h;
        q = fmaf(h, h, q);
    }
    sarr[wid][lane] = s;
    qarr[wid][lane] = q;
    __syncthreads();
    if (threadIdx.x < 32) {
        float ss = 0.f, qq = 0.f;
        #pragma unroll
        for (int w = 0; w < 16; w++) { ss += sarr[w][threadIdx.x]; qq += qarr[w][threadIdx.x]; }
        g_sp[threadIdx.x * 512 + blockIdx.x]        = ss;
        g_sp[(32 + threadIdx.x) * 512 + blockIdx.x] = qq;
    }
    // ---- last block finalizes BN stats ----
    // release: every thread fences its writes, barrier, THEN thread 0 increments.
    __threadfence();
    __syncthreads();
    if (threadIdx.x == 0) {
        unsigned old = atomicAdd(&g_cnt[layer], 1);
        is_last = (old == gridDim.x - 1);
        if (is_last) g_cnt[layer] = 0;
    }
    __syncthreads();
    if (!is_last) return;
    __threadfence();
    // 16 warps; each warp reduces 4 stat rows of 512 partials
    for (int t = wid; t < 64; t += 16) {
        float a = 0.f;
        #pragma unroll
        for (int i = lane; i < 512; i += 32) a += g_sp[t * 512 + i];
        #pragma unroll
        for (int off = 16; off; off >>= 1) a += __shfl_xor_sync(0xffffffffu, a, off);
        if (lane == 0) statf[t] = a;
    }
    __syncthreads();
    if (threadIdx.x < 32) {
        int c = threadIdx.x;
        float mean = statf[c] * (1.0f / (float)BM);
        float var  = statf[32 + c] * (1.0f / (float)BM) - mean * mean;
        float sc = bng[c] * rsqrtf(var + EPS);
        g_bnsc[layer * 32 + c] = sc;
        g_bnsh[layer * 32 + c] = bnb[c] - mean * sc;
    }
}

// -------------------- K3: z = relu(bn0(h0)) @ [w1;w2]^T  (K=32) --------------------
__global__ void __launch_bounds__(256) k_gemm1(const float* __restrict__ w1,
                                               const float* __restrict__ w2) {
    __shared__ float xs[64][36];
    __shared__ float ws[64][36];
    __shared__ float scale[CC], shift[CC];
    if (threadIdx.x < CC) {
        scale[threadIdx.x] = g_bnsc[threadIdx.x];
        shift[threadIdx.x] = g_bnsh[threadIdx.x];
    }
    __syncthreads();
    int m0 = blockIdx.x * 64, b = blockIdx.y;
    const float* hp = g_h0 + ((size_t)b * MM + m0) * CC;
    for (int i = threadIdx.x; i < 2048; i += 256) {
        int r = i >> 5, c = i & 31;
        float v = hp[i];
        xs[r][c] = fmaxf(fmaf(v, scale[c], shift[c]), 0.f);
    }
    for (int i = threadIdx.x; i < 2048; i += 256) {
        int r = i >> 5, k = i & 31;
        ws[r][k] = (r < 32) ? w1[r*32 + k] : w2[(r-32)*32 + k];
    }
    __syncthreads();
    int tc0 = threadIdx.x & 15, tr0 = threadIdx.x >> 4;
    float acc[4][4] = {};
    #pragma unroll
    for (int k = 0; k < 32; k += 4) {
        float4 av[4], bv[4];
        #pragma unroll
        for (int i = 0; i < 4; i++) av[i] = *(const float4*)&xs[tr0 + 16*i][k];
        #pragma unroll
        for (int j = 0; j < 4; j++) bv[j] = *(const float4*)&ws[tc0 + 16*j][k];
        #pragma unroll
        for (int i = 0; i < 4; i++)
            #pragma unroll
            for (int j = 0; j < 4; j++) {
                acc[i][j] = fmaf(av[i].x, bv[j].x, acc[i][j]);
                acc[i][j] = fmaf(av[i].y, bv[j].y, acc[i][j]);
                acc[i][j] = fmaf(av[i].z, bv[j].z, acc[i][j]);
                acc[i][j] = fmaf(av[i].w, bv[j].w, acc[i][j]);
            }
    }
    float* zp = g_z + ((size_t)b * MM + m0) * 64;
    #pragma unroll
    for (int i = 0; i < 4; i++)
        #pragma unroll
        for (int j = 0; j < 4; j++)
            zp[(tr0 + 16*i) * 64 + tc0 + 16*j] = acc[i][j];
}

// -------------------- K5: FC1 (bn1+relu fused) + last-block FC2 --------------------
// grid (4 o-blocks of 64 outputs, 32 k-chunks of 4096). warp = 8 outputs x 8 batches.
// All 8 warps of a block share the same h1 chunk (L1 broadcast).
__global__ void __launch_bounds__(256) k_fc1(const float* __restrict__ fc1w,
                                             const float* __restrict__ fc1b,
                                             const float* __restrict__ fc2w,
                                             const float* __restrict__ fc2b,
                                             float* __restrict__ out) {
    __shared__ unsigned is_last;
    __shared__ float r1[2048];
    int ob = blockIdx.x, kc = blockIdx.y;
    int wid = threadIdx.x >> 5, lane = threadIdx.x & 31;
    int c0 = (lane * 4) & 31;
    float sc[4], sh[4];
    #pragma unroll
    for (int t = 0; t < 4; t++) { sc[t] = g_bnsc[32 + c0 + t]; sh[t] = g_bnsh[32 + c0 + t]; }
    int obase = ob * 64 + wid * 8;
    const float* wbase = fc1w + (size_t)obase * MC + kc * 4096 + lane * 4;
    const float* hbase = g_h1 + kc * 4096 + lane * 4;
    float acc[8][8];
    #pragma unroll
    for (int o = 0; o < 8; o++)
        #pragma unroll
        for (int b = 0; b < 8; b++) acc[o][b] = 0.f;
    #pragma unroll 1
    for (int q = 0; q < 32; q++) {
        int k = q * 128;
        float4 av[8];
        #pragma unroll
        for (int b = 0; b < 8; b++) {
            float4 hv = *(const float4*)(hbase + (size_t)b * MC + k);
            av[b].x = fmaxf(fmaf(hv.x, sc[0], sh[0]), 0.f);
            av[b].y = fmaxf(fmaf(hv.y, sc[1], sh[1]), 0.f);
            av[b].z = fmaxf(fmaf(hv.z, sc[2], sh[2]), 0.f);
            av[b].w = fmaxf(fmaf(hv.w, sc[3], sh[3]), 0.f);
        }
        #pragma unroll
        for (int o = 0; o < 8; o++) {
            float4 wv = *(const float4*)(wbase + (size_t)o * MC + k);
            #pragma unroll
            for (int b = 0; b < 8; b++) {
                acc[o][b] = fmaf(wv.x, av[b].x, acc[o][b]);
                acc[o][b] = fmaf(wv.y, av[b].y, acc[o][b]);
                acc[o][b] = fmaf(wv.z, av[b].z, acc[o][b]);
                acc[o][b] = fmaf(wv.w, av[b].w, acc[o][b]);
            }
        }
    }
    // warps own distinct outputs: reduce over lanes, write partials directly
    #pragma unroll
    for (int o = 0; o < 8; o++)
        #pragma unroll
        for (int b = 0; b < 8; b++) {
            float v = acc[o][b];
            v += __shfl_down_sync(0xffffffff, v, 16);
            v += __shfl_down_sync(0xffffffff, v, 8);
            v += __shfl_down_sync(0xffffffff, v, 4);
            v += __shfl_down_sync(0xffffffff, v, 2);
            v += __shfl_down_sync(0xffffffff, v, 1);
            if (lane == 0) g_fc1p[kc * 2048 + b * 256 + obase + o] = v;
        }
    // ---- last block: combine split-K, relu, FC2 ----
    // release: every thread fences its writes, barrier, THEN thread 0 increments.
    __threadfence();
    __syncthreads();
    if (threadIdx.x == 0) {
        unsigned old = atomicAdd(&g_cnt[2], 1);
        is_last = (old == gridDim.x * gridDim.y - 1);
        if (is_last) g_cnt[2] = 0;
    }
    __syncthreads();
    if (!is_last) return;
    __threadfence();
    for (int i = threadIdx.x; i < 2048; i += 256) {
        float s = 0.f;
        #pragma unroll
        for (int k2 = 0; k2 < 32; k2++) s += g_fc1p[k2 * 2048 + i];
        r1[i] = fmaxf(s + fc1b[i & 255], 0.f);
    }
    __syncthreads();
    for (int b = 0; b < 8; b++) {
        for (int j = wid; j < 53; j += 8) {
            float a = 0.f;
            #pragma unroll
            for (int o = lane; o < 256; o += 32) a = fmaf(r1[b * 256 + o], fc2w[j * 256 + o], a);
            #pragma unroll
            for (int off = 16; off; off >>= 1) a += __shfl_xor_sync(0xffffffffu, a, off);
            if (lane == 0) out[b * 53 + j] = a + fc2b[j];
        }
    }
}

// -------------------- launch --------------------
extern "C" void kernel_launch(void* const* d_in, const int* in_sizes, int n_in,
                              void* d_out, int out_size) {
    const float* x      = (const float*)d_in[0];
    const float* pseudo = (const float*)d_in[1];
    const int*   L_idx  = (const int*)  d_in[2];
    const float* edge_w = (const float*)d_in[3];
    const float* edge_b = (const float*)d_in[4];
    const float* mu0    = (const float*)d_in[5];
    const float* sg0    = (const float*)d_in[6];
    const float* mu1    = (const float*)d_in[7];
    const float* sg1    = (const float*)d_in[8];
    const float* l1w0   = (const float*)d_in[9];
    const float* l1b0   = (const float*)d_in[10];
    const float* l2w0   = (const float*)d_in[11];
    const float* l2b0   = (const float*)d_in[12];
    const float* l1w1   = (const float*)d_in[13];
    const float* l1b1   = (const float*)d_in[14];
    const float* l2w1   = (const float*)d_in[15];
    const float* l2b1   = (const float*)d_in[16];
    const float* bn_g0  = (const float*)d_in[17];
    const float* bn_b0  = (const float*)d_in[18];
    const float* bn_g1  = (const float*)d_in[19];
    const float* bn_b1  = (const float*)d_in[20];
    const float* fc1w   = (const float*)d_in[21];
    const float* fc1b   = (const float*)d_in[22];
    const float* fc2w   = (const float*)d_in[23];
    const float* fc2b   = (const float*)d_in[24];
    float* out = (float*)d_out;

    k_pre<<<512, 256>>>(x, l1w0, l2w0, pseudo, L_idx, edge_w, edge_b, mu0, sg0, mu1, sg1);
    k_gather<<<512, 512>>>(0, l1b0, l2b0, bn_g0, bn_b0);
    k_gemm1<<<dim3(64, 8), 256>>>(l1w1, l2w1);
    k_gather<<<512, 512>>>(1, l1b1, l2b1, bn_g1, bn_b1);
    k_fc1<<<dim3(4, 32), 256>>>(fc1w, fc1b, fc2w, fc2b, out);
}

// round 5
// speedup vs baseline: 1.3190x; 1.3190x over previous
#include <cuda_runtime.h>
#include <cuda_bf16.h>
#include <math.h>

// Problem constants
#define BB 8
#define MM 4096
#define WW 128
#define CC 32
#define NNB 16
#define BM (BB*MM)            // 32768
#define MC (MM*CC)            // 131072
#define EPS 1e-5f

// -------------------- scratch (device globals; no allocs) --------------------
__device__ float g_attn0[MM*NNB];
__device__ float g_attn1[MM*NNB];
__device__ int   g_nbr  [MM*NNB];
__device__ float g_y [BM*64];        // layer0 GEMM out: [b][m][0..31]=x@w1^T, [32..63]=x@w2^T
__device__ float g_z [BM*64];        // layer1 GEMM out
__device__ float g_h0[BM*CC];        // pre-BN layer0
__device__ float g_h1[BM*CC];        // pre-BN layer1
__device__ float g_sp[64*512];       // per-block BN partials (sum rows 0..31, sq rows 32..63)
__device__ float g_bnsc[64];         // BN scale: [0..31] layer0, [32..63] layer1
__device__ float g_bnsh[64];         // BN shift
__device__ float g_fc1p[16*2048];    // split-K partials for FC1: [kc][b*256+o]
__device__ unsigned g_cnt[4];        // zero-init; self-resetting last-block counters

// packed fp32x2 FMA (Blackwell): d = a*b + d on both 32-bit lanes
__device__ __forceinline__ void ffma2(unsigned long long& d, unsigned long long a, unsigned long long b) {
    asm("fma.rn.f32x2 %0, %1, %2, %0;" : "+l"(d) : "l"(a), "l"(b));
}
__device__ __forceinline__ float f32x2_hsum(unsigned long long v) {
    float lo = __uint_as_float((unsigned)(v & 0xffffffffull));
    float hi = __uint_as_float((unsigned)(v >> 32));
    return lo + hi;
}

// -------------------- K1: fused gemm0 (blocks 0..255) + edge attention (256..511) ----
__global__ void __launch_bounds__(256) k_pre(const float* __restrict__ x,
                       const float* __restrict__ w1, const float* __restrict__ w2,
                       const float* __restrict__ pseudo, const int* __restrict__ L_idx,
                       const float* __restrict__ edge_w, const float* __restrict__ edge_b,
                       const float* __restrict__ mu0, const float* __restrict__ sg0,
                       const float* __restrict__ mu1, const float* __restrict__ sg1) {
    __shared__ float2 xs2[16][129];
    __shared__ float2 ws2[16][65];
    if (blockIdx.x >= 256) {
        // ---------------- attention part: thread-per-edge ----------------
        int e = (blockIdx.x - 256) * blockDim.x + threadIdx.x;  // 0..65535
        int r = e >> 4;
        int lane = threadIdx.x & 31;
        int nb = L_idx[e] - r * MM;
        float2 p = *(const float2*)(pseudo + e * 2);
        float emb[5];
        #pragma unroll
        for (int d = 0; d < 5; d++)
            emb[d] = fmaf(p.x, edge_w[d*2], fmaf(p.y, edge_w[d*2+1], edge_b[d]));
        float w0 = 0.f, w1v = 0.f;
        #pragma unroll
        for (int j = 0; j < 4; j++) {
            float q0 = 0.f, q1 = 0.f;
            #pragma unroll
            for (int d = 0; d < 5; d++) {
                float u0 = emb[d] - mu0[j*5+d]; q0 = fmaf(u0*u0, sg0[j*5+d], q0);
                float u1 = emb[d] - mu1[j*5+d]; q1 = fmaf(u1*u1, sg1[j*5+d], q1);
            }
            w0  += __expf(-0.5f * q0);
            w1v += __expf(-0.5f * q1);
        }
        float mx0 = w0, mx1 = w1v;
        #pragma unroll
        for (int off = 8; off; off >>= 1) {
            mx0 = fmaxf(mx0, __shfl_xor_sync(0xffffffffu, mx0, off));
            mx1 = fmaxf(mx1, __shfl_xor_sync(0xffffffffu, mx1, off));
        }
        float e0 = __expf(w0 - mx0), e1 = __expf(w1v - mx1);
        float s0 = e0, s1 = e1;
        #pragma unroll
        for (int off = 8; off; off >>= 1) {
            s0 += __shfl_xor_sync(0xffffffffu, s0, off);
            s1 += __shfl_xor_sync(0xffffffffu, s1, off);
        }
        // dedup: `.at[].set` keeps the LAST duplicate -> only highest lane survives
        unsigned segmask = (lane < 16) ? 0x0000FFFFu : 0xFFFF0000u;
        unsigned m = __match_any_sync(0xffffffffu, nb) & segmask;
        bool keep = (lane == (31 - __clz(m)));
        g_attn0[e] = keep ? e0 / s0 : 0.f;
        g_attn1[e] = keep ? e1 / s1 : 0.f;
        g_nbr[e]   = nb;
        return;
    }
    // ---------------- gemm0: y = x @ [w1;w2]^T, tile 128x64, FFMA2 ----------------
    int m0 = (blockIdx.x & 31) * 128;
    int b  = blockIdx.x >> 5;
    const float* xp = x + ((size_t)b * MM + m0) * WW;
    int tc = threadIdx.x & 15, tr = threadIdx.x >> 4;
    unsigned long long acc[8][4];
    #pragma unroll
    for (int i = 0; i < 8; i++)
        #pragma unroll
        for (int j = 0; j < 4; j++) acc[i][j] = 0ull;

    #pragma unroll 1
    for (int kc = 0; kc < 4; kc++) {
        for (int i = threadIdx.x; i < 1024; i += 256) {
            int r = i >> 3, q = i & 7;
            float4 v = *(const float4*)(xp + r * WW + kc * 32 + q * 4);
            xs2[2*q  ][r] = make_float2(v.x, v.y);
            xs2[2*q+1][r] = make_float2(v.z, v.w);
        }
        for (int i = threadIdx.x; i < 512; i += 256) {
            int r = i >> 3, q = i & 7;
            const float* wp = (r < 32) ? (w1 + r * WW) : (w2 + (r - 32) * WW);
            float4 v = *(const float4*)(wp + kc * 32 + q * 4);
            ws2[2*q  ][r] = make_float2(v.x, v.y);
            ws2[2*q+1][r] = make_float2(v.z, v.w);
        }
        __syncthreads();
        #pragma unroll 4
        for (int kp = 0; kp < 16; kp++) {
            unsigned long long av[8], bv[4];
            #pragma unroll
            for (int i = 0; i < 8; i++) av[i] = *(const unsigned long long*)&xs2[kp][tr + 16*i];
            #pragma unroll
            for (int j = 0; j < 4; j++) bv[j] = *(const unsigned long long*)&ws2[kp][tc + 16*j];
            #pragma unroll
            for (int i = 0; i < 8; i++)
                #pragma unroll
                for (int j = 0; j < 4; j++) ffma2(acc[i][j], av[i], bv[j]);
        }
        __syncthreads();
    }
    float* yp = g_y + ((size_t)b * MM + m0) * 64;
    #pragma unroll
    for (int i = 0; i < 8; i++)
        #pragma unroll
        for (int j = 0; j < 4; j++)
            yp[(tr + 16*i) * 64 + tc + 16*j] = f32x2_hsum(acc[i][j]);
}

// -------------------- K2/K4: gather + BN partials + last-block BN finalize --------------------
// 512 blocks x 512 threads; warp handles 4 (b,m) rows; lane = channel.
// attn/nbr fetched 16-wide by lanes 0..15 then shfl-broadcast (kills 32 uniform LDGs/row).
__global__ void __launch_bounds__(512) k_gather(int layer,
                                                const float* __restrict__ b1,
                                                const float* __restrict__ b2,
                                                const float* __restrict__ bng,
                                                const float* __restrict__ bnb) {
    __shared__ float sarr[16][33];
    __shared__ float qarr[16][33];
    __shared__ float statf[64];
    __shared__ unsigned is_last;
    int wid = threadIdx.x >> 5, lane = threadIdx.x & 31;
    const float* ysrc = layer ? g_z : g_y;
    const float* attn = layer ? g_attn1 : g_attn0;
    float*       hout = layer ? g_h1 : g_h0;
    float bias = b1[lane] + b2[lane];
    float s = 0.f, q = 0.f;
    int base = blockIdx.x * 64 + wid * 4;
    #pragma unroll
    for (int rr = 0; rr < 4; rr++) {
        int gw = base + rr;
        int b  = gw >> 12, m = gw & (MM - 1);
        const float* yb = ysrc + (size_t)b * MM * 64;
        // lane-parallel fetch of the 16 (attn, nbr) pairs, then broadcast
        float a_v = attn[m * NNB + (lane & 15)];
        int   n_v = g_nbr[m * NNB + (lane & 15)];
        float acc = 0.f;
        #pragma unroll
        for (int n = 0; n < NNB; n++) {
            float a  = __shfl_sync(0xffffffffu, a_v, n);
            int   nb = __shfl_sync(0xffffffffu, n_v, n);
            acc = fmaf(a, yb[(size_t)nb * 64 + lane], acc);
        }
        float h = acc + yb[(size_t)m * 64 + 32 + lane] + bias;
        hout[(size_t)gw * CC + lane] = h;
        s += h;
        q = fmaf(h, h, q);
    }
    sarr[wid][lane] = s;
    qarr[wid][lane] = q;
    __syncthreads();
    if (threadIdx.x < 32) {
        float ss = 0.f, qq = 0.f;
        #pragma unroll
        for (int w = 0; w < 16; w++) { ss += sarr[w][threadIdx.x]; qq += qarr[w][threadIdx.x]; }
        g_sp[threadIdx.x * 512 + blockIdx.x]        = ss;
        g_sp[(32 + threadIdx.x) * 512 + blockIdx.x] = qq;
    }
    // ---- last block finalizes BN stats (fence -> barrier -> counter) ----
    __threadfence();
    __syncthreads();
    if (threadIdx.x == 0) {
        unsigned old = atomicAdd(&g_cnt[layer], 1);
        is_last = (old == gridDim.x - 1);
        if (is_last) g_cnt[layer] = 0;
    }
    __syncthreads();
    if (!is_last) return;
    __threadfence();
    for (int t = wid; t < 64; t += 16) {
        float a = 0.f;
        #pragma unroll
        for (int i = lane; i < 512; i += 32) a += g_sp[t * 512 + i];
        #pragma unroll
        for (int off = 16; off; off >>= 1) a += __shfl_xor_sync(0xffffffffu, a, off);
        if (lane == 0) statf[t] = a;
    }
    __syncthreads();
    if (threadIdx.x < 32) {
        int c = threadIdx.x;
        float mean = statf[c] * (1.0f / (float)BM);
        float var  = statf[32 + c] * (1.0f / (float)BM) - mean * mean;
        float sc = bng[c] * rsqrtf(var + EPS);
        g_bnsc[layer * 32 + c] = sc;
        g_bnsh[layer * 32 + c] = bnb[c] - mean * sc;
    }
}

// -------------------- K3: z = relu(bn0(h0)) @ [w1;w2]^T  (K=32) --------------------
__global__ void __launch_bounds__(256) k_gemm1(const float* __restrict__ w1,
                                               const float* __restrict__ w2) {
    __shared__ float xs[64][36];
    __shared__ float ws[64][36];
    __shared__ float scale[CC], shift[CC];
    if (threadIdx.x < CC) {
        scale[threadIdx.x] = g_bnsc[threadIdx.x];
        shift[threadIdx.x] = g_bnsh[threadIdx.x];
    }
    __syncthreads();
    int m0 = blockIdx.x * 64, b = blockIdx.y;
    const float* hp = g_h0 + ((size_t)b * MM + m0) * CC;
    for (int i = threadIdx.x; i < 2048; i += 256) {
        int r = i >> 5, c = i & 31;
        float v = hp[i];
        xs[r][c] = fmaxf(fmaf(v, scale[c], shift[c]), 0.f);
    }
    for (int i = threadIdx.x; i < 2048; i += 256) {
        int r = i >> 5, k = i & 31;
        ws[r][k] = (r < 32) ? w1[r*32 + k] : w2[(r-32)*32 + k];
    }
    __syncthreads();
    int tc0 = threadIdx.x & 15, tr0 = threadIdx.x >> 4;
    float acc[4][4] = {};
    #pragma unroll
    for (int k = 0; k < 32; k += 4) {
        float4 av[4], bv[4];
        #pragma unroll
        for (int i = 0; i < 4; i++) av[i] = *(const float4*)&xs[tr0 + 16*i][k];
        #pragma unroll
        for (int j = 0; j < 4; j++) bv[j] = *(const float4*)&ws[tc0 + 16*j][k];
        #pragma unroll
        for (int i = 0; i < 4; i++)
            #pragma unroll
            for (int j = 0; j < 4; j++) {
                acc[i][j] = fmaf(av[i].x, bv[j].x, acc[i][j]);
                acc[i][j] = fmaf(av[i].y, bv[j].y, acc[i][j]);
                acc[i][j] = fmaf(av[i].z, bv[j].z, acc[i][j]);
                acc[i][j] = fmaf(av[i].w, bv[j].w, acc[i][j]);
            }
    }
    float* zp = g_z + ((size_t)b * MM + m0) * 64;
    #pragma unroll
    for (int i = 0; i < 4; i++)
        #pragma unroll
        for (int j = 0; j < 4; j++)
            zp[(tr0 + 16*i) * 64 + tc0 + 16*j] = acc[i][j];
}

// -------------------- K5: FC1 (R2 tiling: 32 ob x 16 kc), bn1+relu fused --------------------
__global__ void __launch_bounds__(256, 2) k_fc1(const float* __restrict__ fc1w) {
    __shared__ float wpart[8][64];
    int ob = blockIdx.x, kc = blockIdx.y;
    int wid = threadIdx.x >> 5, lane = threadIdx.x & 31;
    int c0 = (lane * 4) & 31;
    float sc[4], sh[4];
    #pragma unroll
    for (int t = 0; t < 4; t++) { sc[t] = g_bnsc[32 + c0 + t]; sh[t] = g_bnsh[32 + c0 + t]; }
    int kbase = kc * 8192 + wid * 1024 + lane * 4;
    float acc[8][8];
    #pragma unroll
    for (int o = 0; o < 8; o++)
        #pragma unroll
        for (int b = 0; b < 8; b++) acc[o][b] = 0.f;
    const float* wbase = fc1w + (size_t)(ob * 8) * MC;
    #pragma unroll 1
    for (int q = 0; q < 8; q++) {
        int k = kbase + q * 128;
        float4 av[8];
        #pragma unroll
        for (int b = 0; b < 8; b++) {
            float4 hv = *(const float4*)(g_h1 + (size_t)b * MC + k);
            av[b].x = fmaxf(fmaf(hv.x, sc[0], sh[0]), 0.f);
            av[b].y = fmaxf(fmaf(hv.y, sc[1], sh[1]), 0.f);
            av[b].z = fmaxf(fmaf(hv.z, sc[2], sh[2]), 0.f);
            av[b].w = fmaxf(fmaf(hv.w, sc[3], sh[3]), 0.f);
        }
        #pragma unroll
        for (int o = 0; o < 8; o++) {
            float4 wv = *(const float4*)(wbase + (size_t)o * MC + k);
            #pragma unroll
            for (int b = 0; b < 8; b++) {
                acc[o][b] = fmaf(wv.x, av[b].x, acc[o][b]);
                acc[o][b] = fmaf(wv.y, av[b].y, acc[o][b]);
                acc[o][b] = fmaf(wv.z, av[b].z, acc[o][b]);
                acc[o][b] = fmaf(wv.w, av[b].w, acc[o][b]);
            }
        }
    }
    #pragma unroll
    for (int o = 0; o < 8; o++)
        #pragma unroll
        for (int b = 0; b < 8; b++) {
            float v = acc[o][b];
            v += __shfl_down_sync(0xffffffff, v, 16);
            v += __shfl_down_sync(0xffffffff, v, 8);
            v += __shfl_down_sync(0xffffffff, v, 4);
            v += __shfl_down_sync(0xffffffff, v, 2);
            v += __shfl_down_sync(0xffffffff, v, 1);
            if (lane == 0) wpart[wid][o * 8 + b] = v;
        }
    __syncthreads();
    if (threadIdx.x < 64) {
        int o = threadIdx.x >> 3, b = threadIdx.x & 7;
        float s = 0.f;
        #pragma unroll
        for (int w = 0; w < 8; w++) s += wpart[w][o * 8 + b];
        g_fc1p[kc * 2048 + b * 256 + ob * 8 + o] = s;
    }
}

// -------------------- K6: combine split-K, relu, FC2 (block per batch) --------------------
__global__ void __launch_bounds__(256) k_fc2(const float* __restrict__ fc1b,
                                             const float* __restrict__ fc2w,
                                             const float* __restrict__ fc2b,
                                             float* __restrict__ out) {
    __shared__ float r1[256];
    int b = blockIdx.x;
    int t = threadIdx.x;
    float s = 0.f;
    #pragma unroll
    for (int kc = 0; kc < 16; kc++) s += g_fc1p[kc * 2048 + b * 256 + t];
    r1[t] = fmaxf(s + fc1b[t], 0.f);
    __syncthreads();
    int wid = t >> 5, lane = t & 31;
    for (int j = wid; j < 53; j += 8) {
        float acc = 0.f;
        #pragma unroll
        for (int o = lane; o < 256; o += 32) acc = fmaf(r1[o], fc2w[j * 256 + o], acc);
        #pragma unroll
        for (int off = 16; off; off >>= 1) acc += __shfl_xor_sync(0xffffffffu, acc, off);
        if (lane == 0) out[b * 53 + j] = acc + fc2b[j];
    }
}

// -------------------- launch --------------------
extern "C" void kernel_launch(void* const* d_in, const int* in_sizes, int n_in,
                              void* d_out, int out_size) {
    const float* x      = (const float*)d_in[0];
    const float* pseudo = (const float*)d_in[1];
    const int*   L_idx  = (const int*)  d_in[2];
    const float* edge_w = (const float*)d_in[3];
    const float* edge_b = (const float*)d_in[4];
    const float* mu0    = (const float*)d_in[5];
    const float* sg0    = (const float*)d_in[6];
    const float* mu1    = (const float*)d_in[7];
    const float* sg1    = (const float*)d_in[8];
    const float* l1w0   = (const float*)d_in[9];
    const float* l1b0   = (const float*)d_in[10];
    const float* l2w0   = (const float*)d_in[11];
    const float* l2b0   = (const float*)d_in[12];
    const float* l1w1   = (const float*)d_in[13];
    const float* l1b1   = (const float*)d_in[14];
    const float* l2w1   = (const float*)d_in[15];
    const float* l2b1   = (const float*)d_in[16];
    const float* bn_g0  = (const float*)d_in[17];
    const float* bn_b0  = (const float*)d_in[18];
    const float* bn_g1  = (const float*)d_in[19];
    const float* bn_b1  = (const float*)d_in[20];
    const float* fc1w   = (const float*)d_in[21];
    const float* fc1b   = (const float*)d_in[22];
    const float* fc2w   = (const float*)d_in[23];
    const float* fc2b   = (const float*)d_in[24];
    float* out = (float*)d_out;

    k_pre<<<512, 256>>>(x, l1w0, l2w0, pseudo, L_idx, edge_w, edge_b, mu0, sg0, mu1, sg1);
    k_gather<<<512, 512>>>(0, l1b0, l2b0, bn_g0, bn_b0);
    k_gemm1<<<dim3(64, 8), 256>>>(l1w1, l2w1);
    k_gather<<<512, 512>>>(1, l1b1, l2b1, bn_g1, bn_b1);
    k_fc1<<<dim3(32, 16), 256>>>(fc1w);
    k_fc2<<<8, 256>>>(fc1b, fc2w, fc2b, out);
}